// round 6
// baseline (speedup 1.0000x reference)
#include <cuda_runtime.h>
#include <cuda_bf16.h>

// CLUB loss, single-pass formulation.
//   result = ( -0.5*P + 0.5/N * sum_d [ X2_d*S_d - 2*X_d*T_d ] ) / N
// with  P    = sum_{i,d} (x^2 - 2*x*mu) * exp(-lv)
//       X_d  = sum_i x,   X2_d = sum_i x^2
//       S_d  = sum_i exp(-lv),   T_d = sum_i mu*exp(-lv)
// (The mu^2 terms cancel between positive and negative.)
//
// Shapes: x (16,512,32,32) f32, p_mu (16384,512) f32, p_logvar (16384,512) f32.

#define NB   16
#define DD   512
#define HW   1024
#define NTOK (NB * HW)          // 16384
#define NSLICE 256              // 256 slices of 64 tokens
#define SLICE_TOK 64
#define PITCH 65                // smem tile pitch (floats)

// Stateless per-launch scratch (fully overwritten each launch).
// gPart layout: [a][slice][d]  (d innermost -> coalesced stage-2 reads)
__device__ float        gPart[4 * NSLICE * DD];   // 2 MB
__device__ float        gP[2048];                 // per-block scalar partials
__device__ double       gAcc2[4 * 8 * DD];        // [a][slice-octant][d]
__device__ unsigned int gTicket;                  // reset to 0 by last block each launch

// Grid: 2048 blocks = 8 feature-chunks (64 each) x 256 token-slices (64 each).
// ~25KB smem -> 8 blocks/SM -> wave capacity 1184 -> 1.73 waves (balanced tail).
__global__ __launch_bounds__(256) void club_main_kernel(
    const float* __restrict__ x,
    const float* __restrict__ pmu,
    const float* __restrict__ plv)
{
    __shared__ float xs[64 * PITCH];      // x tile: [feature][token], 16.6 KB
    __shared__ float red[4][8][64];       // cross-warp reduction buffer
    __shared__ float spc[8];

    const int tid  = threadIdx.x;
    const int w    = tid >> 5;
    const int lane = tid & 31;
    const int q    = lane & 15;           // float4 feature column (features q*4..q*4+3)
    const int th   = lane >> 4;           // token parity within pass
    const int bid  = blockIdx.x;

    const int dc    = (bid & 7) << 6;     // feature-chunk base (0..448)
    const int slice = bid >> 3;           // token-slice index  (0..255)
    const int i0    = slice << 6;         // first global token of slice
    const int b     = i0 >> 10;           // batch (slice never crosses batch)
    const int hw0   = i0 & 1023;
    const float* xb = x + ((size_t)((b << 9) + dc) << 10) + hw0;   // x[b, dc, hw0]

    // ---- stage x tile: 64 feature-rows x 64 tokens (16 float4 cols) ----
    // Warp covers 2 rows x 16 cols -> coalesced 256B segments, ~2-way STS conflicts.
    #pragma unroll
    for (int k = 0; k < 4; ++k) {
        const int qq  = tid + (k << 8);        // 0..1023
        const int row = qq >> 4;               // 0..63
        const int c4  = qq & 15;               // float4 column
        float4 v = reinterpret_cast<const float4*>(xb + (size_t)row * HW)[c4];
        float* d = &xs[row * PITCH + (c4 << 2)];
        d[0] = v.x; d[1] = v.y; d[2] = v.z; d[3] = v.w;
    }
    __syncthreads();

    // ---- main loop: warp w owns tokens [8w, 8w+8); pass p covers 2 tokens ----
    float sX[4]  = {0.f, 0.f, 0.f, 0.f};
    float sXX[4] = {0.f, 0.f, 0.f, 0.f};
    float sS[4]  = {0.f, 0.f, 0.f, 0.f};
    float sT[4]  = {0.f, 0.f, 0.f, 0.f};
    float accP   = 0.f;

    const int tbase = (w << 3) + th;                       // first token of this thread
    const float* mp = pmu + (size_t)(i0 + tbase) * DD + dc + (q << 2);
    const float* lp = plv + (size_t)(i0 + tbase) * DD + dc + (q << 2);

    float4 mv  = *reinterpret_cast<const float4*>(mp);
    float4 lv4 = *reinterpret_cast<const float4*>(lp);

    #pragma unroll
    for (int p = 0; p < 4; ++p) {
        float4 mn = make_float4(0.f, 0.f, 0.f, 0.f);
        float4 ln = make_float4(0.f, 0.f, 0.f, 0.f);
        if (p < 3) {                                       // prefetch next pass
            mn = *reinterpret_cast<const float4*>(mp + (size_t)(2 * DD) * (p + 1));
            ln = *reinterpret_cast<const float4*>(lp + (size_t)(2 * DD) * (p + 1));
        }
        const int tl = tbase + (p << 1);
        const float* xrow = &xs[(q << 2) * PITCH + tl];
        float xv[4];
        xv[0] = xrow[0];
        xv[1] = xrow[PITCH];
        xv[2] = xrow[2 * PITCH];
        xv[3] = xrow[3 * PITCH];
        const float mm[4] = {mv.x, mv.y, mv.z, mv.w};
        const float ll[4] = {lv4.x, lv4.y, lv4.z, lv4.w};
        #pragma unroll
        for (int j = 0; j < 4; ++j) {
            const float iv = __expf(-ll[j]);
            const float xx = xv[j] * xv[j];
            const float e  = fmaf(xv[j] * mm[j], -2.0f, xx);   // x^2 - 2*x*mu
            accP   = fmaf(e, iv, accP);
            sS[j] += iv;
            sT[j]  = fmaf(mm[j], iv, sT[j]);
            sX[j] += xv[j];
            sXX[j] += xx;
        }
        mv = mn; lv4 = ln;
    }

    // ---- combine the two token-halves (lane ^ 16 holds same features) ----
    #pragma unroll
    for (int j = 0; j < 4; ++j) {
        sX[j]  += __shfl_xor_sync(0xffffffffu, sX[j],  16);
        sXX[j] += __shfl_xor_sync(0xffffffffu, sXX[j], 16);
        sS[j]  += __shfl_xor_sync(0xffffffffu, sS[j],  16);
        sT[j]  += __shfl_xor_sync(0xffffffffu, sT[j],  16);
    }
    #pragma unroll
    for (int o = 16; o; o >>= 1) accP += __shfl_xor_sync(0xffffffffu, accP, o);

    if (lane < 16) {
        #pragma unroll
        for (int j = 0; j < 4; ++j) {
            red[0][w][(q << 2) + j] = sX[j];
            red[1][w][(q << 2) + j] = sXX[j];
            red[2][w][(q << 2) + j] = sS[j];
            red[3][w][(q << 2) + j] = sT[j];
        }
    }
    if (lane == 0) spc[w] = accP;
    __syncthreads();

    {
        const int a  = tid >> 6;      // accumulator 0..3
        const int dd = tid & 63;      // feature within chunk
        float s = 0.f;
        #pragma unroll
        for (int ww = 0; ww < 8; ++ww) s += red[a][ww][dd];
        gPart[(a * NSLICE + slice) * DD + dc + dd] = s;   // coalesced
    }
    if (tid == 0) {
        float s = 0.f;
        #pragma unroll
        for (int ww = 0; ww < 8; ++ww) s += spc[ww];
        gP[bid] = s;
    }
}

// Stage 2 + finalize, fused via last-block ticket.
// 128 blocks x 128 threads. Block b: a = b>>5, slice-octant so = (b>>2)&7,
// d-range dr = b&3. Each thread sums 32 slices for one d, with 4 independent
// double accumulators (chain length 8).
__global__ __launch_bounds__(128) void club_reduce_final(float* __restrict__ out)
{
    const int tid = threadIdx.x;
    const int b   = blockIdx.x;
    const int a   = b >> 5;
    const int so  = (b >> 2) & 7;
    const int dr  = b & 3;
    const int d   = (dr << 7) + tid;

    const float* p = &gPart[((a * NSLICE) + (so << 5)) * DD + d];
    double acc0 = 0.0, acc1 = 0.0, acc2 = 0.0, acc3 = 0.0;
    #pragma unroll
    for (int k = 0; k < 8; ++k) {
        const float* pk = p + (size_t)(k << 2) * DD;
        acc0 += (double)pk[0];
        acc1 += (double)pk[(size_t)DD];
        acc2 += (double)pk[(size_t)2 * DD];
        acc3 += (double)pk[(size_t)3 * DD];
    }
    gAcc2[((a << 3) + so) * DD + d] = (acc0 + acc1) + (acc2 + acc3);

    __shared__ bool amLast;
    __threadfence();
    if (tid == 0) {
        unsigned v = atomicAdd(&gTicket, 1u);
        amLast = (v == 127u);
    }
    __syncthreads();
    if (!amLast) return;

    // Last block: combine. volatile -> see other blocks' writes.
    volatile double* vA = gAcc2;
    double term = 0.0, psum = 0.0;
    #pragma unroll
    for (int k = 0; k < 4; ++k) {
        const int dd = tid + (k << 7);
        double A[4];
        #pragma unroll
        for (int aa = 0; aa < 4; ++aa) {
            double s0 = 0.0, s1 = 0.0;
            #pragma unroll
            for (int oo = 0; oo < 8; oo += 2) {
                s0 += vA[((aa << 3) + oo) * DD + dd];
                s1 += vA[((aa << 3) + oo + 1) * DD + dd];
            }
            A[aa] = s0 + s1;
        }
        term += A[1] * A[2] - 2.0 * A[0] * A[3];   // XX*S - 2*X*T
    }
    #pragma unroll
    for (int k = 0; k < 16; ++k) psum += (double)gP[tid + (k << 7)];

    #pragma unroll
    for (int o = 16; o; o >>= 1) {
        term += __shfl_xor_sync(0xffffffffu, term, o);
        psum += __shfl_xor_sync(0xffffffffu, psum, o);
    }
    __shared__ double sd[4], sp[4];
    const int wz = tid >> 5;
    if ((tid & 31) == 0) { sd[wz] = term; sp[wz] = psum; }
    __syncthreads();
    if (tid == 0) {
        const double td = sd[0] + sd[1] + sd[2] + sd[3];
        const double tp = sp[0] + sp[1] + sp[2] + sp[3];
        const double N  = (double)NTOK;
        out[0] = (float)((-0.5 * tp + 0.5 * td / N) / N);
        gTicket = 0u;                 // restore invariant for next replay
    }
}

extern "C" void kernel_launch(void* const* d_in, const int* in_sizes, int n_in,
                              void* d_out, int out_size)
{
    const float* x   = (const float*)d_in[0];
    const float* pmu = (const float*)d_in[1];
    const float* plv = (const float*)d_in[2];
    float* out = (float*)d_out;

    club_main_kernel<<<2048, 256>>>(x, pmu, plv);
    club_reduce_final<<<128, 128>>>(out);
}

// round 7
// speedup vs baseline: 1.2826x; 1.2826x over previous
#include <cuda_runtime.h>
#include <cuda_bf16.h>

// CLUB loss, single-pass formulation.
//   result = ( -0.5*P + 0.5/N * sum_d [ X2_d*S_d - 2*X_d*T_d ] ) / N
// with  P    = sum_{i,d} (x^2 - 2*x*mu) * exp(-lv)
//       X_d  = sum_i x,   X2_d = sum_i x^2
//       S_d  = sum_i exp(-lv),   T_d = sum_i mu*exp(-lv)
// (The mu^2 terms cancel between positive and negative.)
//
// Shapes: x (16,512,32,32) f32, p_mu (16384,512) f32, p_logvar (16384,512) f32.

#define NB   16
#define DD   512
#define HW   1024
#define NTOK (NB * HW)          // 16384
#define NSLICE 128
#define PITCH 129               // smem tile pitch (floats); 129 % 32 == 1

// Stateless per-launch scratch (fully overwritten each launch).
// gPart layout: [a][slice][d]  (d innermost -> coalesced stage-2 reads)
__device__ float gPart[4 * NSLICE * DD];   // 1 MB
__device__ float gP[1024];                 // per-block scalar partials
__device__ float gAccQ[4 * 4 * DD];        // [a][slice-quarter][d], 32 KB

// Grid: 1024 blocks = 8 feature-chunks (64 each) x 128 token-slices (128 each).
__global__ __launch_bounds__(256) void club_main_kernel(
    const float* __restrict__ x,
    const float* __restrict__ pmu,
    const float* __restrict__ plv)
{
    __shared__ float xs[64 * PITCH];      // x tile: [feature][token], 33 KB
    __shared__ float red[4][8][64];       // cross-warp reduction buffer
    __shared__ float spc[8];

    const int tid  = threadIdx.x;
    const int w    = tid >> 5;
    const int lane = tid & 31;
    const int q    = lane & 15;           // float4 feature column (features q*4..q*4+3)
    const int th   = lane >> 4;           // token parity within pass
    const int bid  = blockIdx.x;

    const int dc    = (bid & 7) << 6;     // feature-chunk base (0..448)
    const int slice = bid >> 3;           // token-slice index  (0..127)
    const int i0    = slice << 7;         // first global token of slice
    const int b     = i0 >> 10;           // batch (slice never crosses batch)
    const int hw0   = i0 & 1023;
    const float* xb = x + ((size_t)((b << 9) + dc) << 10) + hw0;   // x[b, dc, hw0]

    // ---- stage x tile: 64 feature-rows x 128 tokens (32 float4 cols) ----
    // Warp covers 4 rows x 8 float4-cols -> conflict-free STS, 512B/row-chunk LDG.
    #pragma unroll
    for (int k = 0; k < 8; ++k) {
        const int qq  = tid + (k << 8);        // 0..2047
        const int c4l = qq & 7;
        const int row = (qq >> 3) & 63;
        const int c4h = qq >> 9;
        const int col = (c4h << 3) + c4l;      // float4 column 0..31
        float4 v = reinterpret_cast<const float4*>(xb + (size_t)row * HW)[col];
        float* d = &xs[row * PITCH + (col << 2)];
        d[0] = v.x; d[1] = v.y; d[2] = v.z; d[3] = v.w;
    }
    __syncthreads();

    // ---- main loop: warp w owns tokens [16w, 16w+16); pass p covers 2 tokens ----
    float sX[4]  = {0.f, 0.f, 0.f, 0.f};
    float sXX[4] = {0.f, 0.f, 0.f, 0.f};
    float sS[4]  = {0.f, 0.f, 0.f, 0.f};
    float sT[4]  = {0.f, 0.f, 0.f, 0.f};
    float accP   = 0.f;

    const int tbase = (w << 4) + th;                       // first token of this thread
    const float* mp = pmu + (size_t)(i0 + tbase) * DD + dc + (q << 2);
    const float* lp = plv + (size_t)(i0 + tbase) * DD + dc + (q << 2);

    float4 mv  = *reinterpret_cast<const float4*>(mp);
    float4 lv4 = *reinterpret_cast<const float4*>(lp);

    #pragma unroll
    for (int p = 0; p < 8; ++p) {
        float4 mn = make_float4(0.f, 0.f, 0.f, 0.f);
        float4 ln = make_float4(0.f, 0.f, 0.f, 0.f);
        if (p < 7) {                                       // prefetch next pass
            mn = *reinterpret_cast<const float4*>(mp + (size_t)(2 * DD) * (p + 1));
            ln = *reinterpret_cast<const float4*>(lp + (size_t)(2 * DD) * (p + 1));
        }
        const int tl = tbase + (p << 1);
        const float* xrow = &xs[(q << 2) * PITCH + tl];
        float xv[4];
        xv[0] = xrow[0];
        xv[1] = xrow[PITCH];
        xv[2] = xrow[2 * PITCH];
        xv[3] = xrow[3 * PITCH];
        const float mm[4] = {mv.x, mv.y, mv.z, mv.w};
        const float ll[4] = {lv4.x, lv4.y, lv4.z, lv4.w};
        #pragma unroll
        for (int j = 0; j < 4; ++j) {
            const float iv = __expf(-ll[j]);
            const float xx = xv[j] * xv[j];
            const float e  = fmaf(xv[j] * mm[j], -2.0f, xx);   // x^2 - 2*x*mu
            accP   = fmaf(e, iv, accP);
            sS[j] += iv;
            sT[j]  = fmaf(mm[j], iv, sT[j]);
            sX[j] += xv[j];
            sXX[j] += xx;
        }
        mv = mn; lv4 = ln;
    }

    // ---- combine the two token-halves (lane ^ 16 holds same features) ----
    #pragma unroll
    for (int j = 0; j < 4; ++j) {
        sX[j]  += __shfl_xor_sync(0xffffffffu, sX[j],  16);
        sXX[j] += __shfl_xor_sync(0xffffffffu, sXX[j], 16);
        sS[j]  += __shfl_xor_sync(0xffffffffu, sS[j],  16);
        sT[j]  += __shfl_xor_sync(0xffffffffu, sT[j],  16);
    }
    #pragma unroll
    for (int o = 16; o; o >>= 1) accP += __shfl_xor_sync(0xffffffffu, accP, o);

    if (lane < 16) {
        #pragma unroll
        for (int j = 0; j < 4; ++j) {
            red[0][w][(q << 2) + j] = sX[j];
            red[1][w][(q << 2) + j] = sXX[j];
            red[2][w][(q << 2) + j] = sS[j];
            red[3][w][(q << 2) + j] = sT[j];
        }
    }
    if (lane == 0) spc[w] = accP;
    __syncthreads();

    {
        const int a  = tid >> 6;      // accumulator 0..3
        const int dd = tid & 63;      // feature within chunk
        float s = 0.f;
        #pragma unroll
        for (int ww = 0; ww < 8; ++ww) s += red[a][ww][dd];
        gPart[(a * NSLICE + slice) * DD + dc + dd] = s;   // coalesced
    }
    if (tid == 0) {
        float s = 0.f;
        #pragma unroll
        for (int ww = 0; ww < 8; ++ww) s += spc[ww];
        gP[bid] = s;
    }
}

// Stage 2: 64 blocks x 128 threads. Block b: a = b>>4, slice-quarter sq=(b>>2)&3,
// d-range dr = b&3. Each thread sums 32 slices for one d with 4 independent
// fp32 accumulators (dep chain 8 x 4cyc), loads coalesced across threads.
__global__ __launch_bounds__(128) void club_reduce_kernel()
{
    const int tid = threadIdx.x;
    const int b   = blockIdx.x;
    const int a   = b >> 4;
    const int sq  = (b >> 2) & 3;
    const int dr  = b & 3;
    const int d   = (dr << 7) + tid;

    const float* p = &gPart[((a * NSLICE) + (sq << 5)) * DD + d];
    float a0 = 0.f, a1 = 0.f, a2 = 0.f, a3 = 0.f;
    #pragma unroll
    for (int k = 0; k < 8; ++k) {
        const float* pk = p + (size_t)(k << 2) * DD;
        a0 += pk[0];
        a1 += pk[(size_t)DD];
        a2 += pk[(size_t)2 * DD];
        a3 += pk[(size_t)3 * DD];
    }
    gAccQ[((a << 2) + sq) * DD + d] = (a0 + a1) + (a2 + a3);
}

// Stage 3: tiny single-block finalize (reads 32 KB + 4 KB, all coalesced).
__global__ __launch_bounds__(512) void club_final_kernel(float* __restrict__ out)
{
    __shared__ double sd[512];
    __shared__ double sp[512];
    const int tid = threadIdx.x;   // tid == feature d

    double A[4];
    #pragma unroll
    for (int aa = 0; aa < 4; ++aa) {
        A[aa] = (double)gAccQ[((aa << 2) + 0) * DD + tid]
              + (double)gAccQ[((aa << 2) + 1) * DD + tid]
              + (double)gAccQ[((aa << 2) + 2) * DD + tid]
              + (double)gAccQ[((aa << 2) + 3) * DD + tid];
    }
    const double X = A[0], XX = A[1], S = A[2], T = A[3];

    sd[tid] = XX * S - 2.0 * X * T;
    sp[tid] = (double)gP[tid] + (double)gP[tid + 512];
    __syncthreads();

    #pragma unroll
    for (int o = 256; o; o >>= 1) {
        if (tid < o) { sd[tid] += sd[tid + o]; sp[tid] += sp[tid + o]; }
        __syncthreads();
    }
    if (tid == 0) {
        const double N = (double)NTOK;
        out[0] = (float)((-0.5 * sp[0] + 0.5 * sd[0] / N) / N);
    }
}

extern "C" void kernel_launch(void* const* d_in, const int* in_sizes, int n_in,
                              void* d_out, int out_size)
{
    const float* x   = (const float*)d_in[0];
    const float* pmu = (const float*)d_in[1];
    const float* plv = (const float*)d_in[2];
    float* out = (float*)d_out;

    club_main_kernel<<<1024, 256>>>(x, pmu, plv);
    club_reduce_kernel<<<64, 128>>>();
    club_final_kernel<<<1, 512>>>(out);
}